// round 5
// baseline (speedup 1.0000x reference)
#include <cuda_runtime.h>
#include <math.h>

#define N_NODES 50000
#define F_IN    128
#define H1      128
#define H2      64
#define E_TRAIN 600000
#define E_SCORE 200000

// Scratch buffers (device globals — no allocation allowed)
__device__ float g_deg [N_NODES];
__device__ float g_dinv[N_NODES];
__device__ float g_h0  [N_NODES * H1];   // x @ W1
__device__ float g_agg1[N_NODES * H1];   // layer-1 aggregated (pre-relu)
__device__ float g_h2p [N_NODES * H2];   // relu(agg1) @ W2
__device__ float g_agg2[N_NODES * H2];   // layer-2 output h2

// ---------------------------------------------------------------- degree
__global__ void k_deg_init() {
    int i = blockIdx.x * blockDim.x + threadIdx.x;
    if (i < N_NODES) g_deg[i] = 1.0f;   // self-loop
}

__global__ void k_deg_count(const int* __restrict__ ei) {
    int e = blockIdx.x * blockDim.x + threadIdx.x;
    if (e < E_TRAIN) atomicAdd(&g_deg[ei[E_TRAIN + e]], 1.0f);  // col = target
}

__global__ void k_dinv() {
    int i = blockIdx.x * blockDim.x + threadIdx.x;
    if (i < N_NODES) g_dinv[i] = rsqrtf(g_deg[i]);
}

// ---------------------------------------------------------------- GEMM1: g_h0 = x @ W1   [50000x128] @ [128x128]
// Block tile 64 rows x 128 cols, 256 threads, thread tile 4 rows x 8 cols.
// cols are interleaved: thread covers cols {cg + 16*j}, cg = tx%16 -> conflict-free smem reads.
__global__ __launch_bounds__(256) void k_gemm1(const float* __restrict__ x,
                                               const float* __restrict__ W) {
    __shared__ float xs[64][17];        // [row][k-chunk] padded
    __shared__ float Ws[16 * 128];      // [kk][col]
    const int tx  = threadIdx.x;
    const int cg  = tx & 15;            // col group
    const int rg  = tx >> 4;            // row group (0..15), 4 rows each
    const int row0 = blockIdx.x * 64;

    float acc[4][8];
#pragma unroll
    for (int r = 0; r < 4; r++)
#pragma unroll
        for (int j = 0; j < 8; j++) acc[r][j] = 0.0f;

    for (int k0 = 0; k0 < F_IN; k0 += 16) {
        // stage xs: 64x16 = 1024 floats, 4 per thread (float4 from gmem)
        {
            int i0 = tx * 4;
            int r  = i0 >> 4;
            int kk = i0 & 15;
            int grow = row0 + r;
            float4 v = make_float4(0.f, 0.f, 0.f, 0.f);
            if (grow < N_NODES)
                v = *(const float4*)&x[grow * F_IN + k0 + kk];
            xs[r][kk + 0] = v.x; xs[r][kk + 1] = v.y;
            xs[r][kk + 2] = v.z; xs[r][kk + 3] = v.w;
        }
        // stage Ws: 16x128 = 2048 floats, 8 per thread, coalesced
#pragma unroll
        for (int q = 0; q < 8; q++) {
            int idx = tx + 256 * q;
            Ws[idx] = W[(k0 + (idx >> 7)) * H1 + (idx & 127)];
        }
        __syncthreads();

#pragma unroll
        for (int kk = 0; kk < 16; kk++) {
            float xa[4], wb[8];
#pragma unroll
            for (int r = 0; r < 4; r++) xa[r] = xs[rg * 4 + r][kk];
#pragma unroll
            for (int j = 0; j < 8; j++) wb[j] = Ws[kk * 128 + cg + 16 * j];
#pragma unroll
            for (int r = 0; r < 4; r++)
#pragma unroll
                for (int j = 0; j < 8; j++) acc[r][j] += xa[r] * wb[j];
        }
        __syncthreads();
    }

#pragma unroll
    for (int r = 0; r < 4; r++) {
        int grow = row0 + rg * 4 + r;
        if (grow < N_NODES) {
#pragma unroll
            for (int j = 0; j < 8; j++)
                g_h0[grow * H1 + cg + 16 * j] = acc[r][j];
        }
    }
}

// ---------------------------------------------------------------- agg1 init: self-loop + bias
__global__ void k_agg1_init(const float* __restrict__ b1) {
    int t = blockIdx.x * blockDim.x + threadIdx.x;
    if (t >= N_NODES * 32) return;          // 32 float4 per node
    int node = t >> 5, q = t & 31;
    float s = g_dinv[node]; s *= s;
    float4 h  = *(const float4*)&g_h0[node * H1 + q * 4];
    float4 bb = *(const float4*)&b1[q * 4];
    float4 o;
    o.x = h.x * s + bb.x; o.y = h.y * s + bb.y;
    o.z = h.z * s + bb.z; o.w = h.w * s + bb.w;
    *(float4*)&g_agg1[node * H1 + q * 4] = o;
}

// ---------------------------------------------------------------- agg1 edges: warp per edge, 128 feats
__global__ __launch_bounds__(256) void k_agg1_edges(const int* __restrict__ ei) {
    int w = (blockIdx.x * blockDim.x + threadIdx.x) >> 5;
    if (w >= E_TRAIN) return;
    int lane = threadIdx.x & 31;
    int src = ei[w];                // row (source j)
    int dst = ei[E_TRAIN + w];      // col (target i)
    float norm = g_dinv[src] * g_dinv[dst];
    float4 v = *(const float4*)&g_h0[src * H1 + lane * 4];
    float* d = &g_agg1[dst * H1 + lane * 4];
    atomicAdd(d + 0, v.x * norm);
    atomicAdd(d + 1, v.y * norm);
    atomicAdd(d + 2, v.z * norm);
    atomicAdd(d + 3, v.w * norm);
}

// ---------------------------------------------------------------- GEMM2: g_h2p = relu(g_agg1) @ W2  [50000x128]@[128x64]
// Block tile 64 rows x 64 cols, 256 threads, thread tile 4x4 (cols cg + 16*j).
__global__ __launch_bounds__(256) void k_gemm2(const float* __restrict__ W2) {
    __shared__ float xs[64][17];
    __shared__ float Ws[16 * 64];
    const int tx  = threadIdx.x;
    const int cg  = tx & 15;
    const int rg  = tx >> 4;
    const int row0 = blockIdx.x * 64;

    float acc[4][4];
#pragma unroll
    for (int r = 0; r < 4; r++)
#pragma unroll
        for (int j = 0; j < 4; j++) acc[r][j] = 0.0f;

    for (int k0 = 0; k0 < H1; k0 += 16) {
        {
            int i0 = tx * 4;
            int r  = i0 >> 4;
            int kk = i0 & 15;
            int grow = row0 + r;
            float4 v = make_float4(0.f, 0.f, 0.f, 0.f);
            if (grow < N_NODES)
                v = *(const float4*)&g_agg1[grow * H1 + k0 + kk];
            xs[r][kk + 0] = fmaxf(v.x, 0.f); xs[r][kk + 1] = fmaxf(v.y, 0.f);
            xs[r][kk + 2] = fmaxf(v.z, 0.f); xs[r][kk + 3] = fmaxf(v.w, 0.f);
        }
#pragma unroll
        for (int q = 0; q < 4; q++) {
            int idx = tx + 256 * q;               // 1024 = 16*64
            Ws[idx] = W2[(k0 + (idx >> 6)) * H2 + (idx & 63)];
        }
        __syncthreads();

#pragma unroll
        for (int kk = 0; kk < 16; kk++) {
            float xa[4], wb[4];
#pragma unroll
            for (int r = 0; r < 4; r++) xa[r] = xs[rg * 4 + r][kk];
#pragma unroll
            for (int j = 0; j < 4; j++) wb[j] = Ws[kk * 64 + cg + 16 * j];
#pragma unroll
            for (int r = 0; r < 4; r++)
#pragma unroll
                for (int j = 0; j < 4; j++) acc[r][j] += xa[r] * wb[j];
        }
        __syncthreads();
    }

#pragma unroll
    for (int r = 0; r < 4; r++) {
        int grow = row0 + rg * 4 + r;
        if (grow < N_NODES) {
#pragma unroll
            for (int j = 0; j < 4; j++)
                g_h2p[grow * H2 + cg + 16 * j] = acc[r][j];
        }
    }
}

// ---------------------------------------------------------------- agg2 init
__global__ void k_agg2_init(const float* __restrict__ b2) {
    int t = blockIdx.x * blockDim.x + threadIdx.x;
    if (t >= N_NODES * 16) return;          // 16 float4 per node
    int node = t >> 4, q = t & 15;
    float s = g_dinv[node]; s *= s;
    float4 h  = *(const float4*)&g_h2p[node * H2 + q * 4];
    float4 bb = *(const float4*)&b2[q * 4];
    float4 o;
    o.x = h.x * s + bb.x; o.y = h.y * s + bb.y;
    o.z = h.z * s + bb.z; o.w = h.w * s + bb.w;
    *(float4*)&g_agg2[node * H2 + q * 4] = o;
}

// ---------------------------------------------------------------- agg2 edges: warp per edge, 64 feats (float2/lane)
__global__ __launch_bounds__(256) void k_agg2_edges(const int* __restrict__ ei) {
    int w = (blockIdx.x * blockDim.x + threadIdx.x) >> 5;
    if (w >= E_TRAIN) return;
    int lane = threadIdx.x & 31;
    int src = ei[w];
    int dst = ei[E_TRAIN + w];
    float norm = g_dinv[src] * g_dinv[dst];
    float2 v = *(const float2*)&g_h2p[src * H2 + lane * 2];
    float* d = &g_agg2[dst * H2 + lane * 2];
    atomicAdd(d + 0, v.x * norm);
    atomicAdd(d + 1, v.y * norm);
}

// ---------------------------------------------------------------- score: warp per edge, dot over 64 dims
__global__ __launch_bounds__(256) void k_score(const int* __restrict__ pos,
                                               const int* __restrict__ neg,
                                               float* __restrict__ out) {
    int w = (blockIdx.x * blockDim.x + threadIdx.x) >> 5;
    if (w >= 2 * E_SCORE) return;
    int lane = threadIdx.x & 31;
    int src, dst;
    if (w < E_SCORE) { src = pos[w];            dst = pos[E_SCORE + w]; }
    else             { int e = w - E_SCORE; src = neg[e]; dst = neg[E_SCORE + e]; }
    float2 a = *(const float2*)&g_agg2[src * H2 + lane * 2];
    float2 b = *(const float2*)&g_agg2[dst * H2 + lane * 2];
    float s = a.x * b.x + a.y * b.y;
#pragma unroll
    for (int o = 16; o; o >>= 1) s += __shfl_xor_sync(0xFFFFFFFFu, s, o);
    if (lane == 0) out[w] = s;
}

// ----------------------------------------------------------------
extern "C" void kernel_launch(void* const* d_in, const int* in_sizes, int n_in,
                              void* d_out, int out_size) {
    const float* x    = (const float*)d_in[0];
    const int*   tr   = (const int*)  d_in[1];   // [2, 600000]
    const int*   pos  = (const int*)  d_in[2];   // [2, 200000]
    const int*   neg  = (const int*)  d_in[3];   // [2, 200000]
    const float* W1   = (const float*)d_in[4];
    const float* b1   = (const float*)d_in[5];
    const float* W2   = (const float*)d_in[6];
    const float* b2   = (const float*)d_in[7];
    float* out = (float*)d_out;

    k_deg_init <<<(N_NODES + 255) / 256, 256>>>();
    k_deg_count<<<(E_TRAIN + 255) / 256, 256>>>(tr);
    k_dinv     <<<(N_NODES + 255) / 256, 256>>>();

    k_gemm1<<<(N_NODES + 63) / 64, 256>>>(x, W1);
    k_agg1_init<<<(N_NODES * 32 + 255) / 256, 256>>>(b1);
    k_agg1_edges<<<(E_TRAIN * 32 + 255) / 256, 256>>>(tr);

    k_gemm2<<<(N_NODES + 63) / 64, 256>>>(W2);
    k_agg2_init<<<(N_NODES * 16 + 255) / 256, 256>>>(b2);
    k_agg2_edges<<<(E_TRAIN * 32 + 255) / 256, 256>>>(tr);

    k_score<<<(2 * E_SCORE * 32 + 255) / 256, 256>>>(pos, neg, out);
}

// round 7
// speedup vs baseline: 2.0629x; 2.0629x over previous
#include <cuda_runtime.h>
#include <math.h>

#define N_NODES 50000
#define F_IN    128
#define H1      128
#define H2      64
#define E_TRAIN 600000
#define E_SCORE 200000
#define NB_SCAN 196                     // ceil(50000/256)

// Scratch buffers (device globals — no allocation allowed)
__device__ float g_dinv  [N_NODES];
__device__ int   g_cnt   [N_NODES];         // in-degree (no self-loop)
__device__ int   g_rowptr[N_NODES + 1];     // CSR row pointers (by dst)
__device__ int   g_cursor[N_NODES];         // fill cursors
__device__ int   g_bsum  [256];             // scan block sums
__device__ int   g_boff  [256];             // scanned block offsets
__device__ int   g_esrc  [E_TRAIN];         // dst-sorted source indices
__device__ float g_h0    [N_NODES * H1];    // x @ W1
__device__ float g_agg1  [N_NODES * H1];    // layer-1 aggregated (pre-relu)
__device__ float g_h2p   [N_NODES * H2];    // relu(agg1) @ W2
__device__ float g_agg2  [N_NODES * H2];    // layer-2 output h2

// ---------------------------------------------------------------- degree/CSR build
__global__ void k_zero_cnt() {
    int i = blockIdx.x * blockDim.x + threadIdx.x;
    if (i < N_NODES) g_cnt[i] = 0;
}

__global__ void k_count(const int* __restrict__ ei) {
    int e = blockIdx.x * blockDim.x + threadIdx.x;
    if (e < E_TRAIN) atomicAdd(&g_cnt[ei[E_TRAIN + e]], 1);   // col = target
}

__global__ void k_dinv() {
    int i = blockIdx.x * blockDim.x + threadIdx.x;
    if (i < N_NODES) g_dinv[i] = rsqrtf((float)(g_cnt[i] + 1));   // +1 self-loop
}

// Exclusive scan over g_cnt -> g_rowptr, 3 phases.
__global__ void k_scan1() {
    __shared__ int sd[256];
    int t = threadIdx.x;
    int i = blockIdx.x * 256 + t;
    int v = (i < N_NODES) ? g_cnt[i] : 0;
    sd[t] = v;
    __syncthreads();
#pragma unroll
    for (int o = 1; o < 256; o <<= 1) {
        int u = (t >= o) ? sd[t - o] : 0;
        __syncthreads();
        sd[t] += u;
        __syncthreads();
    }
    if (i < N_NODES) g_rowptr[i] = sd[t] - v;     // exclusive
    if (t == 255) g_bsum[blockIdx.x] = sd[255];
}

__global__ void k_scan2() {
    __shared__ int sd[256];
    int t = threadIdx.x;
    int v = (t < NB_SCAN) ? g_bsum[t] : 0;
    sd[t] = v;
    __syncthreads();
#pragma unroll
    for (int o = 1; o < 256; o <<= 1) {
        int u = (t >= o) ? sd[t - o] : 0;
        __syncthreads();
        sd[t] += u;
        __syncthreads();
    }
    g_boff[t] = sd[t] - v;                         // exclusive
}

__global__ void k_scan3() {
    int i = blockIdx.x * blockDim.x + threadIdx.x;
    if (i < N_NODES) {
        int r = g_rowptr[i] + g_boff[i >> 8];
        g_rowptr[i] = r;
        g_cursor[i] = r;
    }
    if (i == 0) g_rowptr[N_NODES] = E_TRAIN;
}

__global__ void k_fill(const int* __restrict__ ei) {
    int e = blockIdx.x * blockDim.x + threadIdx.x;
    if (e >= E_TRAIN) return;
    int dst = ei[E_TRAIN + e];
    int p = atomicAdd(&g_cursor[dst], 1);
    g_esrc[p] = ei[e];
}

// ---------------------------------------------------------------- GEMM1: g_h0 = x @ W1   [50000x128] @ [128x128]
__global__ __launch_bounds__(256) void k_gemm1(const float* __restrict__ x,
                                               const float* __restrict__ W) {
    __shared__ float xs[64][17];
    __shared__ float Ws[16 * 128];
    const int tx  = threadIdx.x;
    const int cg  = tx & 15;
    const int rg  = tx >> 4;
    const int row0 = blockIdx.x * 64;

    float acc[4][8];
#pragma unroll
    for (int r = 0; r < 4; r++)
#pragma unroll
        for (int j = 0; j < 8; j++) acc[r][j] = 0.0f;

    for (int k0 = 0; k0 < F_IN; k0 += 16) {
        {
            int i0 = tx * 4;
            int r  = i0 >> 4;
            int kk = i0 & 15;
            int grow = row0 + r;
            float4 v = make_float4(0.f, 0.f, 0.f, 0.f);
            if (grow < N_NODES)
                v = *(const float4*)&x[grow * F_IN + k0 + kk];
            xs[r][kk + 0] = v.x; xs[r][kk + 1] = v.y;
            xs[r][kk + 2] = v.z; xs[r][kk + 3] = v.w;
        }
#pragma unroll
        for (int q = 0; q < 8; q++) {
            int idx = tx + 256 * q;
            Ws[idx] = W[(k0 + (idx >> 7)) * H1 + (idx & 127)];
        }
        __syncthreads();

#pragma unroll
        for (int kk = 0; kk < 16; kk++) {
            float xa[4], wb[8];
#pragma unroll
            for (int r = 0; r < 4; r++) xa[r] = xs[rg * 4 + r][kk];
#pragma unroll
            for (int j = 0; j < 8; j++) wb[j] = Ws[kk * 128 + cg + 16 * j];
#pragma unroll
            for (int r = 0; r < 4; r++)
#pragma unroll
                for (int j = 0; j < 8; j++) acc[r][j] += xa[r] * wb[j];
        }
        __syncthreads();
    }

#pragma unroll
    for (int r = 0; r < 4; r++) {
        int grow = row0 + rg * 4 + r;
        if (grow < N_NODES) {
#pragma unroll
            for (int j = 0; j < 8; j++)
                g_h0[grow * H1 + cg + 16 * j] = acc[r][j];
        }
    }
}

// ---------------------------------------------------------------- agg1 gather: warp per node, 128 feats (float4/lane)
__global__ __launch_bounds__(256) void k_agg1_gather(const float* __restrict__ b1) {
    int node = (blockIdx.x * blockDim.x + threadIdx.x) >> 5;
    if (node >= N_NODES) return;
    int lane = threadIdx.x & 31;

    float di = g_dinv[node];
    float selfs = di * di;

    float4 acc = *(const float4*)&g_h0[node * H1 + lane * 4];
    float4 bb  = *(const float4*)&b1[lane * 4];
    acc.x = acc.x * selfs + bb.x;
    acc.y = acc.y * selfs + bb.y;
    acc.z = acc.z * selfs + bb.z;
    acc.w = acc.w * selfs + bb.w;

    int s = g_rowptr[node];
    int e = g_rowptr[node + 1];
    for (int k = s; k < e; k++) {
        int src = g_esrc[k];
        float nrm = di * g_dinv[src];
        float4 v = *(const float4*)&g_h0[src * H1 + lane * 4];
        acc.x += v.x * nrm;
        acc.y += v.y * nrm;
        acc.z += v.z * nrm;
        acc.w += v.w * nrm;
    }
    *(float4*)&g_agg1[node * H1 + lane * 4] = acc;
}

// ---------------------------------------------------------------- GEMM2: g_h2p = relu(g_agg1) @ W2  [50000x128]@[128x64]
__global__ __launch_bounds__(256) void k_gemm2(const float* __restrict__ W2) {
    __shared__ float xs[64][17];
    __shared__ float Ws[16 * 64];
    const int tx  = threadIdx.x;
    const int cg  = tx & 15;
    const int rg  = tx >> 4;
    const int row0 = blockIdx.x * 64;

    float acc[4][4];
#pragma unroll
    for (int r = 0; r < 4; r++)
#pragma unroll
        for (int j = 0; j < 4; j++) acc[r][j] = 0.0f;

    for (int k0 = 0; k0 < H1; k0 += 16) {
        {
            int i0 = tx * 4;
            int r  = i0 >> 4;
            int kk = i0 & 15;
            int grow = row0 + r;
            float4 v = make_float4(0.f, 0.f, 0.f, 0.f);
            if (grow < N_NODES)
                v = *(const float4*)&g_agg1[grow * H1 + k0 + kk];
            xs[r][kk + 0] = fmaxf(v.x, 0.f); xs[r][kk + 1] = fmaxf(v.y, 0.f);
            xs[r][kk + 2] = fmaxf(v.z, 0.f); xs[r][kk + 3] = fmaxf(v.w, 0.f);
        }
#pragma unroll
        for (int q = 0; q < 4; q++) {
            int idx = tx + 256 * q;
            Ws[idx] = W2[(k0 + (idx >> 6)) * H2 + (idx & 63)];
        }
        __syncthreads();

#pragma unroll
        for (int kk = 0; kk < 16; kk++) {
            float xa[4], wb[4];
#pragma unroll
            for (int r = 0; r < 4; r++) xa[r] = xs[rg * 4 + r][kk];
#pragma unroll
            for (int j = 0; j < 4; j++) wb[j] = Ws[kk * 64 + cg + 16 * j];
#pragma unroll
            for (int r = 0; r < 4; r++)
#pragma unroll
                for (int j = 0; j < 4; j++) acc[r][j] += xa[r] * wb[j];
        }
        __syncthreads();
    }

#pragma unroll
    for (int r = 0; r < 4; r++) {
        int grow = row0 + rg * 4 + r;
        if (grow < N_NODES) {
#pragma unroll
            for (int j = 0; j < 4; j++)
                g_h2p[grow * H2 + cg + 16 * j] = acc[r][j];
        }
    }
}

// ---------------------------------------------------------------- agg2 gather: half-warp per node, 64 feats (float4/lane16)
__global__ __launch_bounds__(256) void k_agg2_gather(const float* __restrict__ b2) {
    int node = (blockIdx.x * blockDim.x + threadIdx.x) >> 4;
    if (node >= N_NODES) return;
    int lane = threadIdx.x & 15;

    float di = g_dinv[node];
    float selfs = di * di;

    float4 acc = *(const float4*)&g_h2p[node * H2 + lane * 4];
    float4 bb  = *(const float4*)&b2[lane * 4];
    acc.x = acc.x * selfs + bb.x;
    acc.y = acc.y * selfs + bb.y;
    acc.z = acc.z * selfs + bb.z;
    acc.w = acc.w * selfs + bb.w;

    int s = g_rowptr[node];
    int e = g_rowptr[node + 1];
    for (int k = s; k < e; k++) {
        int src = g_esrc[k];
        float nrm = di * g_dinv[src];
        float4 v = *(const float4*)&g_h2p[src * H2 + lane * 4];
        acc.x += v.x * nrm;
        acc.y += v.y * nrm;
        acc.z += v.z * nrm;
        acc.w += v.w * nrm;
    }
    *(float4*)&g_agg2[node * H2 + lane * 4] = acc;
}

// ---------------------------------------------------------------- score: half-warp per edge, dot over 64 dims (float4/lane16)
__global__ __launch_bounds__(256) void k_score(const int* __restrict__ pos,
                                               const int* __restrict__ neg,
                                               float* __restrict__ out) {
    int w = (blockIdx.x * blockDim.x + threadIdx.x) >> 4;
    if (w >= 2 * E_SCORE) return;
    int lane = threadIdx.x & 15;
    int src, dst;
    if (w < E_SCORE) { src = pos[w];            dst = pos[E_SCORE + w]; }
    else             { int e = w - E_SCORE; src = neg[e]; dst = neg[E_SCORE + e]; }
    float4 a = *(const float4*)&g_agg2[src * H2 + lane * 4];
    float4 b = *(const float4*)&g_agg2[dst * H2 + lane * 4];
    float s = a.x * b.x + a.y * b.y + a.z * b.z + a.w * b.w;
#pragma unroll
    for (int o = 8; o; o >>= 1) s += __shfl_xor_sync(0xFFFFFFFFu, s, o);
    if (lane == 0) out[w] = s;
}

// ----------------------------------------------------------------
extern "C" void kernel_launch(void* const* d_in, const int* in_sizes, int n_in,
                              void* d_out, int out_size) {
    const float* x    = (const float*)d_in[0];
    const int*   tr   = (const int*)  d_in[1];   // [2, 600000]
    const int*   pos  = (const int*)  d_in[2];   // [2, 200000]
    const int*   neg  = (const int*)  d_in[3];   // [2, 200000]
    const float* W1   = (const float*)d_in[4];
    const float* b1   = (const float*)d_in[5];
    const float* W2   = (const float*)d_in[6];
    const float* b2   = (const float*)d_in[7];
    float* out = (float*)d_out;

    // CSR build (destination-sorted)
    k_zero_cnt<<<(N_NODES + 255) / 256, 256>>>();
    k_count   <<<(E_TRAIN + 255) / 256, 256>>>(tr);
    k_dinv    <<<(N_NODES + 255) / 256, 256>>>();
    k_scan1   <<<NB_SCAN, 256>>>();
    k_scan2   <<<1, 256>>>();
    k_scan3   <<<(N_NODES + 255) / 256, 256>>>();
    k_fill    <<<(E_TRAIN + 255) / 256, 256>>>(tr);

    // Layer 1
    k_gemm1<<<(N_NODES + 63) / 64, 256>>>(x, W1);
    k_agg1_gather<<<(N_NODES * 32 + 255) / 256, 256>>>(b1);

    // Layer 2
    k_gemm2<<<(N_NODES + 63) / 64, 256>>>(W2);
    k_agg2_gather<<<(N_NODES * 16 + 255) / 256, 256>>>(b2);

    // Scores
    k_score<<<(2 * E_SCORE * 16 + 255) / 256, 256>>>(pos, neg, out);
}